// round 13
// baseline (speedup 1.0000x reference)
#include <cuda_runtime.h>
#include <cuda_fp16.h>
#include <mma.h>
#include <cstdint>

using namespace nvcuda;

#define N_NODES   50000
#define N_EDGES   1600000
#define N_GRAPHS  128
#define IN_CH     64
#define EDGE_DIM  16
#define HID       64
#define N_CLASSES 10
#define N_LAYERS  5
#define BN_EPS    1e-5f

#define MLP_TN    128
#define LDT       72            // padded leading dim for smem tiles
#define SCAN_CHUNK 256
#define N_CHUNKS  ((N_NODES + SCAN_CHUNK - 1) / SCAN_CHUNK)   // 196

// ---------------- scratch (device globals) --------------------------------
__device__ __align__(16) float  g_h[N_NODES * HID];
__device__ __align__(16) __half g_h16[N_NODES * HID];           // fp16 mirror of h
__device__ __align__(16) float  g_z[N_NODES * HID];             // (1+eps)h + aggr
__device__ __align__(16) float  g_zout[N_NODES * HID];
__device__ __align__(16) __half g_e16[(size_t)N_EDGES * HID];   // fp16 edge proj, CSR order
__device__ __align__(16) float  g_stats[N_LAYERS * 2 * HID];    // per-layer sum/sumsq
__device__ __align__(16) float  g_pool[N_GRAPHS * HID];
__device__ __align__(16) float  g_cnt[N_GRAPHS];
// CSR by dst
__device__ int  g_deg[N_NODES];
__device__ int  g_rowptr[N_NODES + 1];
__device__ int  g_cursor[N_NODES];
__device__ int  g_chunk[N_CHUNKS];
__device__ int  g_src[N_EDGES];     // src node per CSR slot
__device__ int  g_dst[N_EDGES];     // dst node per CSR slot
__device__ int  g_eorig[N_EDGES];   // original edge id per CSR slot

// ---------------- projections ---------------------------------------------

// h = x @ Wn + bn ; writes fp32 + fp16 + z-init for layer 0; zeroes g_deg.
__global__ void k_node_proj(const float* __restrict__ x,
                            const float* __restrict__ Wn,
                            const float* __restrict__ bn,
                            const float* __restrict__ eps) {
    __shared__ float Ws[IN_CH * HID];
    __shared__ float bs[HID];
    int t = threadIdx.x;
    for (int i = t; i < IN_CH * HID; i += blockDim.x) Ws[i] = Wn[i];
    if (t < HID) bs[t] = bn[t];
    __syncthreads();
    int gid = blockIdx.x * blockDim.x + t;
    if (gid < N_NODES) g_deg[gid] = 0;
    if (gid >= N_NODES * HID) return;
    int n = gid >> 6, c = gid & 63;
    float acc = bs[c];
    const float* xr = x + (size_t)n * IN_CH;
#pragma unroll 16
    for (int k = 0; k < IN_CH; k++) acc += xr[k] * Ws[k * HID + c];
    g_h[gid] = acc;
    g_h16[gid] = __float2half(acc);
    g_z[gid] = (1.0f + eps[0]) * acc;    // self term for layer 0
}

// e = edge_attr @ We + be -> fp16, iterating over CSR slots (coalesced,
// streaming stores so L2 keeps h16/weights).
__global__ void k_edge_proj(const float* __restrict__ ea,
                            const float* __restrict__ We,
                            const float* __restrict__ be) {
    __shared__ float Ws[EDGE_DIM * HID];
    __shared__ float bs[HID];
    int t = threadIdx.x;
    for (int i = t; i < EDGE_DIM * HID; i += blockDim.x) Ws[i] = We[i];
    if (t < HID) bs[t] = be[t];
    __syncthreads();
    int gid = blockIdx.x * blockDim.x + t;
    if (gid >= N_EDGES * 16) return;
    int slot = gid >> 4, q = gid & 15;
    int edge = g_eorig[slot];
    int c = q * 4;
    float a0 = bs[c], a1 = bs[c + 1], a2 = bs[c + 2], a3 = bs[c + 3];
    const float* er = ea + (size_t)edge * EDGE_DIM;
#pragma unroll
    for (int k = 0; k < EDGE_DIM; k++) {
        float v = er[k];
        const float4 w = *reinterpret_cast<const float4*>(&Ws[k * HID + c]);
        a0 += v * w.x; a1 += v * w.y; a2 += v * w.z; a3 += v * w.w;
    }
    __half2 p01 = __floats2half2_rn(a0, a1);
    __half2 p23 = __floats2half2_rn(a2, a3);
    uint2 pk;
    pk.x = *reinterpret_cast<unsigned*>(&p01);
    pk.y = *reinterpret_cast<unsigned*>(&p23);
    __stcs(reinterpret_cast<uint2*>(&g_e16[(size_t)slot * HID + c]), pk);
}

// ---------------- CSR build ------------------------------------------------

__global__ void k_hist(const int* __restrict__ ei) {
    int e = blockIdx.x * blockDim.x + threadIdx.x;
    if (e >= N_EDGES) return;
    atomicAdd(&g_deg[ei[N_EDGES + e]], 1);
}

__global__ void k_scan_part() {
    __shared__ int sm[SCAN_CHUNK];
    int t = threadIdx.x;
    int idx = blockIdx.x * SCAN_CHUNK + t;
    int v = (idx < N_NODES) ? g_deg[idx] : 0;
    sm[t] = v;
    __syncthreads();
    for (int off = 128; off > 0; off >>= 1) {
        if (t < off) sm[t] += sm[t + off];
        __syncthreads();
    }
    if (t == 0) g_chunk[blockIdx.x] = sm[0];
}

__global__ void k_scan_top() {
    __shared__ int sm[256];
    int t = threadIdx.x;
    sm[t] = (t < N_CHUNKS) ? g_chunk[t] : 0;
    __syncthreads();
    for (int off = 1; off < 256; off <<= 1) {
        int v = (t >= off) ? sm[t - off] : 0;
        __syncthreads();
        sm[t] += v;
        __syncthreads();
    }
    if (t < N_CHUNKS) g_chunk[t] = (t > 0) ? sm[t - 1] : 0;
    if (t == 0) g_rowptr[N_NODES] = N_EDGES;
}

__global__ void k_scan_final() {
    __shared__ int sm[SCAN_CHUNK];
    int t = threadIdx.x;
    int idx = blockIdx.x * SCAN_CHUNK + t;
    int v = (idx < N_NODES) ? g_deg[idx] : 0;
    sm[t] = v;
    __syncthreads();
    for (int off = 1; off < SCAN_CHUNK; off <<= 1) {
        int u = (t >= off) ? sm[t - off] : 0;
        __syncthreads();
        sm[t] += u;
        __syncthreads();
    }
    if (idx < N_NODES) {
        int r = g_chunk[blockIdx.x] + sm[t] - v;   // exclusive
        g_rowptr[idx] = r;
        g_cursor[idx] = r;
    }
}

__global__ void k_scatter(const int* __restrict__ ei) {
    int e = blockIdx.x * blockDim.x + threadIdx.x;
    if (e >= N_EDGES) return;
    int src = ei[e];
    int dst = ei[N_EDGES + e];
    int pos = atomicAdd(&g_cursor[dst], 1);
    g_src[pos] = src;
    g_dst[pos] = dst;
    g_eorig[pos] = e;
}

// zero pool + counts + ALL per-layer BN stats (every launch, before layers)
__global__ void k_init() {
    int gid = blockIdx.x * blockDim.x + threadIdx.x;
    if (gid < N_GRAPHS * HID) g_pool[gid] = 0.0f;
    if (gid < N_GRAPHS) g_cnt[gid] = 0.0f;
    if (gid < N_LAYERS * 2 * HID) g_stats[gid] = 0.0f;
}

// ---------------- per-layer kernels ----------------------------------------

// Edge-parallel message scatter: g_z[dst] += relu(h16[src] + e16)
// 16 threads per CSR slot, 4 channels each. dst-sorted -> red locality.
__global__ void k_msg2() {
    int gid = blockIdx.x * blockDim.x + threadIdx.x;   // exact N_EDGES*16
    int slot = gid >> 4;
    int c = (gid & 15) * 4;
    int src = g_src[slot];
    int dst = g_dst[slot];
    const __half2 zero2 = __float2half2_rn(0.0f);
    uint2 ev = __ldcs(reinterpret_cast<const uint2*>(&g_e16[(size_t)slot * HID + c]));
    uint2 hv = *reinterpret_cast<const uint2*>(&g_h16[(size_t)src * HID + c]);
    __half2 ma = __hmax2(__hadd2(*reinterpret_cast<__half2*>(&hv.x),
                                 *reinterpret_cast<__half2*>(&ev.x)), zero2);
    __half2 mb = __hmax2(__hadd2(*reinterpret_cast<__half2*>(&hv.y),
                                 *reinterpret_cast<__half2*>(&ev.y)), zero2);
    float2 fa = __half22float2(ma), fb = __half22float2(mb);
    float* p = &g_z[(size_t)dst * HID + c];
    asm volatile("red.global.add.v4.f32 [%0], {%1, %2, %3, %4};"
                 :: "l"(p), "f"(fa.x), "f"(fa.y), "f"(fb.x), "f"(fb.y) : "memory");
}

// MLP on tensor cores (tf32, smem pre-converted). 128 nodes/block, 8 warps.
// zout = relu(z @ W1 + b1) @ W2 + b2 ; accumulates BN sum/sumsq.
__global__ void k_mlp_tc(const float* __restrict__ W1, const float* __restrict__ b1,
                         const float* __restrict__ W2, const float* __restrict__ b2,
                         int layer) {
    extern __shared__ float sm[];
    float* zt   = sm;                      // [128][LDT]
    float* w1s  = zt + MLP_TN * LDT;       // [64][LDT]
    float* w2s  = w1s + HID * LDT;         // [64][LDT]
    float* b1s  = w2s + HID * LDT;
    float* b2s  = b1s + HID;
    float* ssum = b2s + HID;
    float* ssq  = ssum + HID;

    int t = threadIdx.x;
    for (int i = t; i < HID * HID; i += 256) {
        int r = i >> 6, c = i & 63;
        w1s[r * LDT + c] = wmma::__float_to_tf32(W1[i]);
        w2s[r * LDT + c] = wmma::__float_to_tf32(W2[i]);
    }
    if (t < HID) { b1s[t] = b1[t]; b2s[t] = b2[t]; ssum[t] = 0.0f; ssq[t] = 0.0f; }
    int node0 = blockIdx.x * MLP_TN;

    for (int i = t; i < MLP_TN * 16; i += 256) {
        int n = i >> 4, kc = (i & 15) * 4;
        int node = node0 + n;
        float4 zv = make_float4(0.f, 0.f, 0.f, 0.f);
        if (node < N_NODES)
            zv = *reinterpret_cast<const float4*>(&g_z[(size_t)node * HID + kc]);
        zt[n * LDT + kc]     = wmma::__float_to_tf32(zv.x);
        zt[n * LDT + kc + 1] = wmma::__float_to_tf32(zv.y);
        zt[n * LDT + kc + 2] = wmma::__float_to_tf32(zv.z);
        zt[n * LDT + kc + 3] = wmma::__float_to_tf32(zv.w);
    }
    __syncthreads();

    int warp = t >> 5, lane = t & 31;
    float* arow = zt + warp * 16 * LDT;

    // ---- GEMM1 ----
    wmma::fragment<wmma::accumulator, 16, 16, 8, float> cf[4];
#pragma unroll
    for (int nt = 0; nt < 4; nt++) wmma::fill_fragment(cf[nt], 0.0f);
#pragma unroll
    for (int k = 0; k < HID; k += 8) {
        wmma::fragment<wmma::matrix_a, 16, 16, 8, wmma::precision::tf32, wmma::row_major> af;
        wmma::load_matrix_sync(af, arow + k, LDT);
#pragma unroll
        for (int nt = 0; nt < 4; nt++) {
            wmma::fragment<wmma::matrix_b, 16, 16, 8, wmma::precision::tf32, wmma::row_major> bf;
            wmma::load_matrix_sync(bf, w1s + k * LDT + nt * 16, LDT);
            wmma::mma_sync(cf[nt], af, bf, cf[nt]);
        }
    }
#pragma unroll
    for (int nt = 0; nt < 4; nt++)
        wmma::store_matrix_sync(arow + nt * 16, cf[nt], LDT, wmma::mem_row_major);
    __syncwarp();
    // bias + relu + tf32-round for GEMM2's A operand
    for (int i = lane; i < 16 * HID; i += 32) {
        int r = i >> 6, c = i & 63;
        arow[r * LDT + c] = wmma::__float_to_tf32(fmaxf(arow[r * LDT + c] + b1s[c], 0.0f));
    }
    __syncwarp();

    // ---- GEMM2 ----
#pragma unroll
    for (int nt = 0; nt < 4; nt++) wmma::fill_fragment(cf[nt], 0.0f);
#pragma unroll
    for (int k = 0; k < HID; k += 8) {
        wmma::fragment<wmma::matrix_a, 16, 16, 8, wmma::precision::tf32, wmma::row_major> af;
        wmma::load_matrix_sync(af, arow + k, LDT);
#pragma unroll
        for (int nt = 0; nt < 4; nt++) {
            wmma::fragment<wmma::matrix_b, 16, 16, 8, wmma::precision::tf32, wmma::row_major> bf;
            wmma::load_matrix_sync(bf, w2s + k * LDT + nt * 16, LDT);
            wmma::mma_sync(cf[nt], af, bf, cf[nt]);
        }
    }
#pragma unroll
    for (int nt = 0; nt < 4; nt++)
        wmma::store_matrix_sync(arow + nt * 16, cf[nt], LDT, wmma::mem_row_major);
    __syncwarp();

#pragma unroll
    for (int half = 0; half < 2; half++) {
        int c = lane + half * 32;
        float s = 0.f, q = 0.f;
#pragma unroll
        for (int r = 0; r < 16; r++) {
            int node = node0 + warp * 16 + r;
            if (node < N_NODES) {
                float v = arow[r * LDT + c] + b2s[c];
                g_zout[(size_t)node * HID + c] = v;
                s += v; q += v * v;
            }
        }
        atomicAdd(&ssum[c], s);
        atomicAdd(&ssq[c], q);
    }
    __syncthreads();
    if (t < HID) {
        atomicAdd(&g_stats[2 * HID * layer + t], ssum[t]);
        atomicAdd(&g_stats[2 * HID * layer + HID + t], ssq[t]);
    }
}

// h = relu(gamma*(zout - mu)*inv_std + beta) + h ; writes fp32 h.
// Not last layer: also write h16 and z-init (1+eps[l+1])*h for next layer.
// Last layer: fuse pooling instead.
__global__ void k_bnapply(const float* __restrict__ gamma,
                          const float* __restrict__ beta,
                          const int* __restrict__ batch,
                          const float* __restrict__ eps,
                          int layer, int do_pool) {
    int gid = blockIdx.x * blockDim.x + threadIdx.x;
    if (gid >= N_NODES * 16) return;
    int c = (gid & 15) * 4;
    const float* st = g_stats + 2 * HID * layer;
    const float invN = 1.0f / (float)N_NODES;
    float4 v = *reinterpret_cast<const float4*>(&g_zout[(size_t)gid * 4]);
    float4 h = *reinterpret_cast<const float4*>(&g_h[(size_t)gid * 4]);
    float r[4] = {v.x, v.y, v.z, v.w};
    float hh[4] = {h.x, h.y, h.z, h.w};
#pragma unroll
    for (int j = 0; j < 4; j++) {
        float mu = st[c + j] * invN;
        float var = st[HID + c + j] * invN - mu * mu;
        float inv = rsqrtf(var + BN_EPS);
        float tt = gamma[c + j] * (r[j] - mu) * inv + beta[c + j];
        r[j] = fmaxf(tt, 0.0f) + hh[j];
    }
    *reinterpret_cast<float4*>(&g_h[(size_t)gid * 4]) = make_float4(r[0], r[1], r[2], r[3]);
    if (!do_pool) {
        __half2 p01 = __floats2half2_rn(r[0], r[1]);
        __half2 p23 = __floats2half2_rn(r[2], r[3]);
        uint2 pk;
        pk.x = *reinterpret_cast<unsigned*>(&p01);
        pk.y = *reinterpret_cast<unsigned*>(&p23);
        *reinterpret_cast<uint2*>(&g_h16[(size_t)gid * 4]) = pk;
        float se = 1.0f + eps[layer + 1];
        *reinterpret_cast<float4*>(&g_z[(size_t)gid * 4]) =
            make_float4(se * r[0], se * r[1], se * r[2], se * r[3]);
    } else {
        int n = gid >> 4;
        int b = batch[n];
        float* p = &g_pool[b * HID + c];
        asm volatile("red.global.add.v4.f32 [%0], {%1, %2, %3, %4};"
                     :: "l"(p), "f"(r[0]), "f"(r[1]), "f"(r[2]), "f"(r[3]) : "memory");
        if ((gid & 15) == 0)
            asm volatile("red.global.add.f32 [%0], %1;" :: "l"(&g_cnt[b]), "f"(1.0f) : "memory");
    }
}

// classifier: one block (64 threads) per graph
__global__ void k_cls(const float* __restrict__ W1, const float* __restrict__ b1,
                      const float* __restrict__ W2, const float* __restrict__ b2,
                      float* __restrict__ out) {
    __shared__ float pr[HID];
    __shared__ float aw[HID];
    int g = blockIdx.x;
    int t = threadIdx.x;
    float cnt = fmaxf(g_cnt[g], 1.0f);
    pr[t] = g_pool[g * HID + t] / cnt;
    __syncthreads();
    float acc = b1[t];
#pragma unroll 8
    for (int k = 0; k < HID; k++) acc += pr[k] * W1[k * HID + t];
    aw[t] = fmaxf(acc, 0.0f);
    __syncthreads();
    if (t < N_CLASSES) {
        float o = b2[t];
#pragma unroll 8
        for (int k = 0; k < HID; k++) o += aw[k] * W2[k * N_CLASSES + t];
        float prob = 1.0f / (1.0f + expf(-o));
        float pred = (prob > 0.5f) ? 1.0f : 0.0f;
        int idx = g * N_CLASSES + t;
        out[idx] = o;
        out[N_GRAPHS * N_CLASSES + idx] = prob;
        out[2 * N_GRAPHS * N_CLASSES + idx] = pred;
        out[3 * N_GRAPHS * N_CLASSES + idx] = pred;
    }
}

// ---------------- launch --------------------------------------------------
extern "C" void kernel_launch(void* const* d_in, const int* in_sizes, int n_in,
                              void* d_out, int out_size) {
    const float* x      = (const float*)d_in[0];
    const int*   ei     = (const int*)  d_in[1];
    const int*   batch  = (const int*)  d_in[2];
    const float* ea     = (const float*)d_in[3];
    const float* Wn     = (const float*)d_in[4];
    const float* bn     = (const float*)d_in[5];
    const float* We     = (const float*)d_in[6];
    const float* be     = (const float*)d_in[7];
    const float* eps    = (const float*)d_in[8];
    const float* mlp_W1 = (const float*)d_in[9];
    const float* mlp_b1 = (const float*)d_in[10];
    const float* mlp_W2 = (const float*)d_in[11];
    const float* mlp_b2 = (const float*)d_in[12];
    const float* bn_g   = (const float*)d_in[13];
    const float* bn_b   = (const float*)d_in[14];
    const float* cls_W1 = (const float*)d_in[15];
    const float* cls_b1 = (const float*)d_in[16];
    const float* cls_W2 = (const float*)d_in[17];
    const float* cls_b2 = (const float*)d_in[18];
    float* out = (float*)d_out;

    const int TPB = 256;
    const int node_blocks   = (N_NODES * HID + TPB - 1) / TPB;   // 12500
    const int node4_blocks  = (N_NODES * 16 + TPB - 1) / TPB;    // 3125
    const int edge16_blocks = (N_EDGES * 16) / TPB;              // 100000
    const int edge_blocks   = (N_EDGES + TPB - 1) / TPB;         // 6250
    const int mlp_blocks    = (N_NODES + MLP_TN - 1) / MLP_TN;   // 391
    const int mlp_smem      = (MLP_TN * LDT + 2 * HID * LDT + 4 * HID) * sizeof(float);
    const int init_blocks   = (N_GRAPHS * HID + TPB - 1) / TPB;  // 32 (covers stats too)

    static bool attr_set = false;
    if (!attr_set) {
        cudaFuncSetAttribute(k_mlp_tc, cudaFuncAttributeMaxDynamicSharedMemorySize, mlp_smem);
        attr_set = true;
    }

    k_node_proj<<<node_blocks, TPB>>>(x, Wn, bn, eps);  // also zeroes g_deg, inits g_z
    k_hist<<<edge_blocks, TPB>>>(ei);
    k_scan_part<<<N_CHUNKS, SCAN_CHUNK>>>();
    k_scan_top<<<1, 256>>>();
    k_scan_final<<<N_CHUNKS, SCAN_CHUNK>>>();
    k_scatter<<<edge_blocks, TPB>>>(ei);
    k_edge_proj<<<edge16_blocks, TPB>>>(ea, We, be);
    k_init<<<init_blocks, TPB>>>();

    for (int l = 0; l < N_LAYERS; l++) {
        k_msg2<<<edge16_blocks, TPB>>>();
        k_mlp_tc<<<mlp_blocks, TPB, mlp_smem>>>(mlp_W1 + l * HID * HID, mlp_b1 + l * HID,
                                                mlp_W2 + l * HID * HID, mlp_b2 + l * HID, l);
        k_bnapply<<<node4_blocks, TPB>>>(bn_g + l * HID, bn_b + l * HID,
                                         batch, eps, l, (l == N_LAYERS - 1) ? 1 : 0);
    }

    k_cls<<<N_GRAPHS, HID>>>(cls_W1, cls_b1, cls_W2, cls_b2, out);
}

// round 14
// speedup vs baseline: 1.3728x; 1.3728x over previous
#include <cuda_runtime.h>
#include <cuda_fp16.h>
#include <mma.h>
#include <cstdint>

using namespace nvcuda;

#define N_NODES   50000
#define N_EDGES   1600000
#define N_GRAPHS  128
#define IN_CH     64
#define EDGE_DIM  16
#define HID       64
#define N_CLASSES 10
#define N_LAYERS  5
#define BN_EPS    1e-5f

#define MLP_TN    128
#define LDT       72            // padded leading dim for smem tiles
#define SCAN_CHUNK 256
#define N_CHUNKS  ((N_NODES + SCAN_CHUNK - 1) / SCAN_CHUNK)   // 196
#define NP_NODES  16            // nodes per node_proj block

// ---------------- scratch (device globals) --------------------------------
__device__ __align__(16) float  g_h[N_NODES * HID];
__device__ __align__(16) __half g_h16[N_NODES * HID];           // fp16 mirror of h
__device__ __align__(16) float  g_z[N_NODES * HID];
__device__ __align__(16) float  g_zout[N_NODES * HID];
__device__ __align__(16) __half g_e16[(size_t)N_EDGES * HID];   // fp16 edge proj, CSR order
__device__ __align__(16) float  g_stats[N_LAYERS * 2 * HID];    // per-layer sum/sumsq
__device__ __align__(16) float  g_pool[N_GRAPHS * HID];
__device__ __align__(16) float  g_cnt[N_GRAPHS];
// CSR by dst
__device__ int  g_deg[N_NODES];
__device__ int  g_rowptr[N_NODES + 1];
__device__ int  g_cursor[N_NODES];
__device__ int  g_chunk[N_CHUNKS];
__device__ int  g_src[N_EDGES];     // src node per CSR slot
__device__ int  g_eorig[N_EDGES];   // original edge id per CSR slot

// ---------------- init: zero deg + pool + cnt + BN stats -------------------
__global__ void k_init() {
    int gid = blockIdx.x * blockDim.x + threadIdx.x;
    if (gid < N_NODES) g_deg[gid] = 0;
    if (gid < N_GRAPHS * HID) g_pool[gid] = 0.0f;
    if (gid < N_GRAPHS) g_cnt[gid] = 0.0f;
    if (gid < N_LAYERS * 2 * HID) g_stats[gid] = 0.0f;
}

// ---------------- projections ---------------------------------------------

// h = x @ Wn + bn ; 16 nodes/block, x staged in smem, writes fp32 + fp16.
__global__ void k_node_proj(const float* __restrict__ x,
                            const float* __restrict__ Wn,
                            const float* __restrict__ bn) {
    __shared__ float Ws[IN_CH * HID];
    __shared__ float bs[HID];
    __shared__ float xs[NP_NODES * IN_CH];
    int t = threadIdx.x;
    for (int i = t; i < IN_CH * HID; i += 256) Ws[i] = Wn[i];
    if (t < HID) bs[t] = bn[t];
    int node0 = blockIdx.x * NP_NODES;
    for (int i = t; i < NP_NODES * IN_CH; i += 256) {
        int idx = node0 * IN_CH + i;
        xs[i] = (idx < N_NODES * IN_CH) ? x[idx] : 0.0f;
    }
    __syncthreads();
    int c = t & 63, nl = t >> 6;
#pragma unroll
    for (int rep = 0; rep < NP_NODES / 4; rep++) {
        int n_local = nl * (NP_NODES / 4) + rep;
        int node = node0 + n_local;
        if (node < N_NODES) {
            float acc = bs[c];
            const float* xr = xs + n_local * IN_CH;
#pragma unroll 16
            for (int k = 0; k < IN_CH; k++) acc += xr[k] * Ws[k * HID + c];
            size_t gid = (size_t)node * HID + c;
            g_h[gid] = acc;
            g_h16[gid] = __float2half(acc);
        }
    }
}

// e = edge_attr @ We + be -> fp16 in CSR order. Coalesced attr load +
// 16-lane shuffle broadcast (1 gmem load/thread); streaming stores.
__global__ void k_edge_proj(const float* __restrict__ ea,
                            const float* __restrict__ We,
                            const float* __restrict__ be) {
    __shared__ float Ws[EDGE_DIM * HID];
    __shared__ float bs[HID];
    int t = threadIdx.x;
    for (int i = t; i < EDGE_DIM * HID; i += blockDim.x) Ws[i] = We[i];
    if (t < HID) bs[t] = be[t];
    __syncthreads();
    int gid = blockIdx.x * blockDim.x + t;     // exact N_EDGES*16
    int slot = gid >> 4;
    int lane = t & 31;
    int q = lane & 15;
    int half = lane & 16;
    int c = q * 4;
    int edge = g_eorig[slot];
    float a = ea[(size_t)edge * EDGE_DIM + q];
    float a0 = bs[c], a1 = bs[c + 1], a2 = bs[c + 2], a3 = bs[c + 3];
#pragma unroll
    for (int k = 0; k < EDGE_DIM; k++) {
        float ak = __shfl_sync(0xffffffffu, a, half | k);
        const float4 w = *reinterpret_cast<const float4*>(&Ws[k * HID + c]);
        a0 += ak * w.x; a1 += ak * w.y; a2 += ak * w.z; a3 += ak * w.w;
    }
    __half2 p01 = __floats2half2_rn(a0, a1);
    __half2 p23 = __floats2half2_rn(a2, a3);
    uint2 pk;
    pk.x = *reinterpret_cast<unsigned*>(&p01);
    pk.y = *reinterpret_cast<unsigned*>(&p23);
    __stcs(reinterpret_cast<uint2*>(&g_e16[(size_t)slot * HID + c]), pk);
}

// ---------------- CSR build ------------------------------------------------

__global__ void k_hist(const int* __restrict__ ei) {
    int e = blockIdx.x * blockDim.x + threadIdx.x;
    if (e >= N_EDGES) return;
    atomicAdd(&g_deg[ei[N_EDGES + e]], 1);
}

__global__ void k_scan_part() {
    __shared__ int sm[SCAN_CHUNK];
    int t = threadIdx.x;
    int idx = blockIdx.x * SCAN_CHUNK + t;
    int v = (idx < N_NODES) ? g_deg[idx] : 0;
    sm[t] = v;
    __syncthreads();
    for (int off = 128; off > 0; off >>= 1) {
        if (t < off) sm[t] += sm[t + off];
        __syncthreads();
    }
    if (t == 0) g_chunk[blockIdx.x] = sm[0];
}

__global__ void k_scan_top() {
    __shared__ int sm[256];
    int t = threadIdx.x;
    sm[t] = (t < N_CHUNKS) ? g_chunk[t] : 0;
    __syncthreads();
    for (int off = 1; off < 256; off <<= 1) {
        int v = (t >= off) ? sm[t - off] : 0;
        __syncthreads();
        sm[t] += v;
        __syncthreads();
    }
    if (t < N_CHUNKS) g_chunk[t] = (t > 0) ? sm[t - 1] : 0;
    if (t == 0) g_rowptr[N_NODES] = N_EDGES;
}

__global__ void k_scan_final() {
    __shared__ int sm[SCAN_CHUNK];
    int t = threadIdx.x;
    int idx = blockIdx.x * SCAN_CHUNK + t;
    int v = (idx < N_NODES) ? g_deg[idx] : 0;
    sm[t] = v;
    __syncthreads();
    for (int off = 1; off < SCAN_CHUNK; off <<= 1) {
        int u = (t >= off) ? sm[t - off] : 0;
        __syncthreads();
        sm[t] += u;
        __syncthreads();
    }
    if (idx < N_NODES) {
        int r = g_chunk[blockIdx.x] + sm[t] - v;   // exclusive
        g_rowptr[idx] = r;
        g_cursor[idx] = r;
    }
}

__global__ void k_scatter(const int* __restrict__ ei) {
    int e = blockIdx.x * blockDim.x + threadIdx.x;
    if (e >= N_EDGES) return;
    int src = ei[e];
    int dst = ei[N_EDGES + e];
    int pos = atomicAdd(&g_cursor[dst], 1);
    g_src[pos] = src;
    g_eorig[pos] = e;
}

// ---------------- per-layer kernels ----------------------------------------

__device__ __forceinline__ void msg_acc(uint2 ev, uint2 hv, const __half2 zero2,
                                        float& a0, float& a1, float& a2, float& a3) {
    __half2 ma = __hmax2(__hadd2(*reinterpret_cast<__half2*>(&hv.x),
                                 *reinterpret_cast<__half2*>(&ev.x)), zero2);
    __half2 mb = __hmax2(__hadd2(*reinterpret_cast<__half2*>(&hv.y),
                                 *reinterpret_cast<__half2*>(&ev.y)), zero2);
    float2 fa = __half22float2(ma), fb = __half22float2(mb);
    a0 += fa.x; a1 += fa.y; a2 += fb.x; a3 += fb.y;
}

// z[n] = (1+eps)*h[n] + sum_j relu(h16[src_j] + e16_j)
// 16 threads per node, 4 channels each; ldcs on e stream; unroll x4 with
// software-pipelined src prefetch.  (R12 version, best known)
__global__ void k_gather(const float* __restrict__ eps, int layer) {
    int t = threadIdx.x;
    int gid = blockIdx.x * blockDim.x + t;
    if (gid >= N_NODES * 16) return;
    int node = gid >> 4;
    int c = (gid & 15) * 4;
    int j = g_rowptr[node];
    int end = g_rowptr[node + 1];
    float a0 = 0.f, a1 = 0.f, a2 = 0.f, a3 = 0.f;
    const __half2 zero2 = __float2half2_rn(0.0f);

    int s0, s1, s2, s3;
    if (j + 4 <= end) {
        s0 = g_src[j]; s1 = g_src[j + 1]; s2 = g_src[j + 2]; s3 = g_src[j + 3];
    }
    for (; j + 4 <= end; ) {
        int c0 = s0, c1 = s1, c2 = s2, c3 = s3;
        int jn = j + 4;
        if (jn + 4 <= end) {
            s0 = g_src[jn]; s1 = g_src[jn + 1]; s2 = g_src[jn + 2]; s3 = g_src[jn + 3];
        }
        uint2 e0 = __ldcs(reinterpret_cast<const uint2*>(&g_e16[(size_t)j * HID + c]));
        uint2 e1 = __ldcs(reinterpret_cast<const uint2*>(&g_e16[(size_t)(j + 1) * HID + c]));
        uint2 e2 = __ldcs(reinterpret_cast<const uint2*>(&g_e16[(size_t)(j + 2) * HID + c]));
        uint2 e3 = __ldcs(reinterpret_cast<const uint2*>(&g_e16[(size_t)(j + 3) * HID + c]));
        uint2 h0 = *reinterpret_cast<const uint2*>(&g_h16[(size_t)c0 * HID + c]);
        uint2 h1 = *reinterpret_cast<const uint2*>(&g_h16[(size_t)c1 * HID + c]);
        uint2 h2 = *reinterpret_cast<const uint2*>(&g_h16[(size_t)c2 * HID + c]);
        uint2 h3 = *reinterpret_cast<const uint2*>(&g_h16[(size_t)c3 * HID + c]);
        msg_acc(e0, h0, zero2, a0, a1, a2, a3);
        msg_acc(e1, h1, zero2, a0, a1, a2, a3);
        msg_acc(e2, h2, zero2, a0, a1, a2, a3);
        msg_acc(e3, h3, zero2, a0, a1, a2, a3);
        j = jn;
    }
    for (; j < end; j++) {
        int sc = g_src[j];
        uint2 e0 = __ldcs(reinterpret_cast<const uint2*>(&g_e16[(size_t)j * HID + c]));
        uint2 h0 = *reinterpret_cast<const uint2*>(&g_h16[(size_t)sc * HID + c]);
        msg_acc(e0, h0, zero2, a0, a1, a2, a3);
    }
    float se = 1.0f + eps[layer];
    float4 hv = *reinterpret_cast<const float4*>(&g_h[(size_t)node * HID + c]);
    float4 z = make_float4(se * hv.x + a0, se * hv.y + a1,
                           se * hv.z + a2, se * hv.w + a3);
    *reinterpret_cast<float4*>(&g_z[(size_t)node * HID + c]) = z;
}

// MLP on tensor cores (tf32, smem pre-converted). 128 nodes/block, 8 warps.
// zout = relu(z @ W1 + b1) @ W2 + b2 ; accumulates BN sum/sumsq.
__global__ void k_mlp_tc(const float* __restrict__ W1, const float* __restrict__ b1,
                         const float* __restrict__ W2, const float* __restrict__ b2,
                         int layer) {
    extern __shared__ float sm[];
    float* zt   = sm;                      // [128][LDT]
    float* w1s  = zt + MLP_TN * LDT;       // [64][LDT]
    float* w2s  = w1s + HID * LDT;         // [64][LDT]
    float* b1s  = w2s + HID * LDT;
    float* b2s  = b1s + HID;
    float* ssum = b2s + HID;
    float* ssq  = ssum + HID;

    int t = threadIdx.x;
    for (int i = t; i < HID * HID; i += 256) {
        int r = i >> 6, c = i & 63;
        w1s[r * LDT + c] = wmma::__float_to_tf32(W1[i]);
        w2s[r * LDT + c] = wmma::__float_to_tf32(W2[i]);
    }
    if (t < HID) { b1s[t] = b1[t]; b2s[t] = b2[t]; ssum[t] = 0.0f; ssq[t] = 0.0f; }
    int node0 = blockIdx.x * MLP_TN;

    for (int i = t; i < MLP_TN * 16; i += 256) {
        int n = i >> 4, kc = (i & 15) * 4;
        int node = node0 + n;
        float4 zv = make_float4(0.f, 0.f, 0.f, 0.f);
        if (node < N_NODES)
            zv = *reinterpret_cast<const float4*>(&g_z[(size_t)node * HID + kc]);
        zt[n * LDT + kc]     = wmma::__float_to_tf32(zv.x);
        zt[n * LDT + kc + 1] = wmma::__float_to_tf32(zv.y);
        zt[n * LDT + kc + 2] = wmma::__float_to_tf32(zv.z);
        zt[n * LDT + kc + 3] = wmma::__float_to_tf32(zv.w);
    }
    __syncthreads();

    int warp = t >> 5, lane = t & 31;
    float* arow = zt + warp * 16 * LDT;

    // ---- GEMM1 ----
    wmma::fragment<wmma::accumulator, 16, 16, 8, float> cf[4];
#pragma unroll
    for (int nt = 0; nt < 4; nt++) wmma::fill_fragment(cf[nt], 0.0f);
#pragma unroll
    for (int k = 0; k < HID; k += 8) {
        wmma::fragment<wmma::matrix_a, 16, 16, 8, wmma::precision::tf32, wmma::row_major> af;
        wmma::load_matrix_sync(af, arow + k, LDT);
#pragma unroll
        for (int nt = 0; nt < 4; nt++) {
            wmma::fragment<wmma::matrix_b, 16, 16, 8, wmma::precision::tf32, wmma::row_major> bf;
            wmma::load_matrix_sync(bf, w1s + k * LDT + nt * 16, LDT);
            wmma::mma_sync(cf[nt], af, bf, cf[nt]);
        }
    }
#pragma unroll
    for (int nt = 0; nt < 4; nt++)
        wmma::store_matrix_sync(arow + nt * 16, cf[nt], LDT, wmma::mem_row_major);
    __syncwarp();
    for (int i = lane; i < 16 * HID; i += 32) {
        int r = i >> 6, c = i & 63;
        arow[r * LDT + c] = wmma::__float_to_tf32(fmaxf(arow[r * LDT + c] + b1s[c], 0.0f));
    }
    __syncwarp();

    // ---- GEMM2 ----
#pragma unroll
    for (int nt = 0; nt < 4; nt++) wmma::fill_fragment(cf[nt], 0.0f);
#pragma unroll
    for (int k = 0; k < HID; k += 8) {
        wmma::fragment<wmma::matrix_a, 16, 16, 8, wmma::precision::tf32, wmma::row_major> af;
        wmma::load_matrix_sync(af, arow + k, LDT);
#pragma unroll
        for (int nt = 0; nt < 4; nt++) {
            wmma::fragment<wmma::matrix_b, 16, 16, 8, wmma::precision::tf32, wmma::row_major> bf;
            wmma::load_matrix_sync(bf, w2s + k * LDT + nt * 16, LDT);
            wmma::mma_sync(cf[nt], af, bf, cf[nt]);
        }
    }
#pragma unroll
    for (int nt = 0; nt < 4; nt++)
        wmma::store_matrix_sync(arow + nt * 16, cf[nt], LDT, wmma::mem_row_major);
    __syncwarp();

#pragma unroll
    for (int half = 0; half < 2; half++) {
        int c = lane + half * 32;
        float s = 0.f, q = 0.f;
#pragma unroll
        for (int r = 0; r < 16; r++) {
            int node = node0 + warp * 16 + r;
            if (node < N_NODES) {
                float v = arow[r * LDT + c] + b2s[c];
                g_zout[(size_t)node * HID + c] = v;
                s += v; q += v * v;
            }
        }
        atomicAdd(&ssum[c], s);
        atomicAdd(&ssq[c], q);
    }
    __syncthreads();
    if (t < HID) {
        atomicAdd(&g_stats[2 * HID * layer + t], ssum[t]);
        atomicAdd(&g_stats[2 * HID * layer + HID + t], ssq[t]);
    }
}

// h = relu(gamma*(zout - mu)*inv_std + beta) + h ; writes fp32 (+ fp16 unless last).
// If last layer, fuse pooling instead.
__global__ void k_bnapply(const float* __restrict__ gamma,
                          const float* __restrict__ beta,
                          const int* __restrict__ batch, int layer, int do_pool) {
    int gid = blockIdx.x * blockDim.x + threadIdx.x;
    if (gid >= N_NODES * 16) return;
    int c = (gid & 15) * 4;
    const float* st = g_stats + 2 * HID * layer;
    const float invN = 1.0f / (float)N_NODES;
    float4 v = *reinterpret_cast<const float4*>(&g_zout[(size_t)gid * 4]);
    float4 h = *reinterpret_cast<const float4*>(&g_h[(size_t)gid * 4]);
    float r[4] = {v.x, v.y, v.z, v.w};
    float hh[4] = {h.x, h.y, h.z, h.w};
#pragma unroll
    for (int j = 0; j < 4; j++) {
        float mu = st[c + j] * invN;
        float var = st[HID + c + j] * invN - mu * mu;
        float inv = rsqrtf(var + BN_EPS);
        float tt = gamma[c + j] * (r[j] - mu) * inv + beta[c + j];
        r[j] = fmaxf(tt, 0.0f) + hh[j];
    }
    *reinterpret_cast<float4*>(&g_h[(size_t)gid * 4]) = make_float4(r[0], r[1], r[2], r[3]);
    if (!do_pool) {
        __half2 p01 = __floats2half2_rn(r[0], r[1]);
        __half2 p23 = __floats2half2_rn(r[2], r[3]);
        uint2 pk;
        pk.x = *reinterpret_cast<unsigned*>(&p01);
        pk.y = *reinterpret_cast<unsigned*>(&p23);
        *reinterpret_cast<uint2*>(&g_h16[(size_t)gid * 4]) = pk;
    } else {
        int n = gid >> 4;
        int b = batch[n];
        float* p = &g_pool[b * HID + c];
        asm volatile("red.global.add.v4.f32 [%0], {%1, %2, %3, %4};"
                     :: "l"(p), "f"(r[0]), "f"(r[1]), "f"(r[2]), "f"(r[3]) : "memory");
        if ((gid & 15) == 0)
            asm volatile("red.global.add.f32 [%0], %1;" :: "l"(&g_cnt[b]), "f"(1.0f) : "memory");
    }
}

// classifier: one block (64 threads) per graph
__global__ void k_cls(const float* __restrict__ W1, const float* __restrict__ b1,
                      const float* __restrict__ W2, const float* __restrict__ b2,
                      float* __restrict__ out) {
    __shared__ float pr[HID];
    __shared__ float aw[HID];
    int g = blockIdx.x;
    int t = threadIdx.x;
    float cnt = fmaxf(g_cnt[g], 1.0f);
    pr[t] = g_pool[g * HID + t] / cnt;
    __syncthreads();
    float acc = b1[t];
#pragma unroll 8
    for (int k = 0; k < HID; k++) acc += pr[k] * W1[k * HID + t];
    aw[t] = fmaxf(acc, 0.0f);
    __syncthreads();
    if (t < N_CLASSES) {
        float o = b2[t];
#pragma unroll 8
        for (int k = 0; k < HID; k++) o += aw[k] * W2[k * N_CLASSES + t];
        float prob = 1.0f / (1.0f + expf(-o));
        float pred = (prob > 0.5f) ? 1.0f : 0.0f;
        int idx = g * N_CLASSES + t;
        out[idx] = o;
        out[N_GRAPHS * N_CLASSES + idx] = prob;
        out[2 * N_GRAPHS * N_CLASSES + idx] = pred;
        out[3 * N_GRAPHS * N_CLASSES + idx] = pred;
    }
}

// ---------------- launch --------------------------------------------------
extern "C" void kernel_launch(void* const* d_in, const int* in_sizes, int n_in,
                              void* d_out, int out_size) {
    const float* x      = (const float*)d_in[0];
    const int*   ei     = (const int*)  d_in[1];
    const int*   batch  = (const int*)  d_in[2];
    const float* ea     = (const float*)d_in[3];
    const float* Wn     = (const float*)d_in[4];
    const float* bn     = (const float*)d_in[5];
    const float* We     = (const float*)d_in[6];
    const float* be     = (const float*)d_in[7];
    const float* eps    = (const float*)d_in[8];
    const float* mlp_W1 = (const float*)d_in[9];
    const float* mlp_b1 = (const float*)d_in[10];
    const float* mlp_W2 = (const float*)d_in[11];
    const float* mlp_b2 = (const float*)d_in[12];
    const float* bn_g   = (const float*)d_in[13];
    const float* bn_b   = (const float*)d_in[14];
    const float* cls_W1 = (const float*)d_in[15];
    const float* cls_b1 = (const float*)d_in[16];
    const float* cls_W2 = (const float*)d_in[17];
    const float* cls_b2 = (const float*)d_in[18];
    float* out = (float*)d_out;

    const int TPB = 256;
    const int np_blocks     = (N_NODES + NP_NODES - 1) / NP_NODES;  // 3125
    const int node4_blocks  = (N_NODES * 16 + TPB - 1) / TPB;    // 3125
    const int edge16_blocks = (N_EDGES * 16) / TPB;              // 100000
    const int edge_blocks   = (N_EDGES + TPB - 1) / TPB;         // 6250
    const int mlp_blocks    = (N_NODES + MLP_TN - 1) / MLP_TN;   // 391
    const int mlp_smem      = (MLP_TN * LDT + 2 * HID * LDT + 4 * HID) * sizeof(float);
    const int init_blocks   = (N_NODES + TPB - 1) / TPB;         // 196 (covers all)

    static bool attr_set = false;
    if (!attr_set) {
        cudaFuncSetAttribute(k_mlp_tc, cudaFuncAttributeMaxDynamicSharedMemorySize, mlp_smem);
        attr_set = true;
    }

    k_init<<<init_blocks, TPB>>>();
    k_node_proj<<<np_blocks, TPB>>>(x, Wn, bn);
    k_hist<<<edge_blocks, TPB>>>(ei);
    k_scan_part<<<N_CHUNKS, SCAN_CHUNK>>>();
    k_scan_top<<<1, 256>>>();
    k_scan_final<<<N_CHUNKS, SCAN_CHUNK>>>();
    k_scatter<<<edge_blocks, TPB>>>(ei);
    k_edge_proj<<<edge16_blocks, TPB>>>(ea, We, be);

    for (int l = 0; l < N_LAYERS; l++) {
        k_gather<<<node4_blocks, TPB>>>(eps, l);
        k_mlp_tc<<<mlp_blocks, TPB, mlp_smem>>>(mlp_W1 + l * HID * HID, mlp_b1 + l * HID,
                                                mlp_W2 + l * HID * HID, mlp_b2 + l * HID, l);
        k_bnapply<<<node4_blocks, TPB>>>(bn_g + l * HID, bn_b + l * HID,
                                         batch, l, (l == N_LAYERS - 1) ? 1 : 0);
    }

    k_cls<<<N_GRAPHS, HID>>>(cls_W1, cls_b1, cls_W2, cls_b2, out);
}

// round 15
// speedup vs baseline: 1.3750x; 1.0015x over previous
#include <cuda_runtime.h>
#include <cuda_fp16.h>
#include <mma.h>
#include <cstdint>

using namespace nvcuda;

#define N_NODES   50000
#define N_EDGES   1600000
#define N_GRAPHS  128
#define IN_CH     64
#define EDGE_DIM  16
#define HID       64
#define N_CLASSES 10
#define N_LAYERS  5
#define BN_EPS    1e-5f

#define MLP_TN    128
#define LDT       72            // padded leading dim for smem tiles
#define SCAN_CHUNK 256
#define N_CHUNKS  ((N_NODES + SCAN_CHUNK - 1) / SCAN_CHUNK)   // 196
#define NP_NODES  16            // nodes per node_proj block

// ---------------- scratch (device globals) --------------------------------
__device__ __align__(16) float  g_h[N_NODES * HID];
__device__ __align__(16) __half g_h16[N_NODES * HID];           // fp16 mirror of h
__device__ __align__(16) float  g_z[N_NODES * HID];
__device__ __align__(16) float  g_zout[N_NODES * HID];
__device__ __align__(16) __half g_e16[(size_t)N_EDGES * HID];   // fp16 edge proj, CSR order
__device__ __align__(16) float  g_stats[N_LAYERS * 2 * HID];    // per-layer sum/sumsq
__device__ __align__(16) float  g_pool[N_GRAPHS * HID];
__device__ __align__(16) float  g_cnt[N_GRAPHS];
// CSR by dst
__device__ int  g_deg[N_NODES];
__device__ int  g_rowptr[N_NODES + 1];
__device__ int  g_cursor[N_NODES];
__device__ int  g_chunk[N_CHUNKS];
__device__ int  g_src[N_EDGES];     // src node per CSR slot
__device__ int  g_eorig[N_EDGES];   // original edge id per CSR slot

// ---------------- init: zero deg + pool + cnt + BN stats -------------------
__global__ void k_init() {
    int gid = blockIdx.x * blockDim.x + threadIdx.x;
    if (gid < N_NODES) g_deg[gid] = 0;
    if (gid < N_GRAPHS * HID) g_pool[gid] = 0.0f;
    if (gid < N_GRAPHS) g_cnt[gid] = 0.0f;
    if (gid < N_LAYERS * 2 * HID) g_stats[gid] = 0.0f;
}

// ---------------- projections ---------------------------------------------

// h = x @ Wn + bn ; 16 nodes/block, x staged in smem, writes fp32 + fp16.
__global__ void k_node_proj(const float* __restrict__ x,
                            const float* __restrict__ Wn,
                            const float* __restrict__ bn) {
    __shared__ float Ws[IN_CH * HID];
    __shared__ float bs[HID];
    __shared__ float xs[NP_NODES * IN_CH];
    int t = threadIdx.x;
    for (int i = t; i < IN_CH * HID; i += 256) Ws[i] = Wn[i];
    if (t < HID) bs[t] = bn[t];
    int node0 = blockIdx.x * NP_NODES;
    for (int i = t; i < NP_NODES * IN_CH; i += 256) {
        int idx = node0 * IN_CH + i;
        xs[i] = (idx < N_NODES * IN_CH) ? x[idx] : 0.0f;
    }
    __syncthreads();
    int c = t & 63, nl = t >> 6;
#pragma unroll
    for (int rep = 0; rep < NP_NODES / 4; rep++) {
        int n_local = nl * (NP_NODES / 4) + rep;
        int node = node0 + n_local;
        if (node < N_NODES) {
            float acc = bs[c];
            const float* xr = xs + n_local * IN_CH;
#pragma unroll 16
            for (int k = 0; k < IN_CH; k++) acc += xr[k] * Ws[k * HID + c];
            size_t gid = (size_t)node * HID + c;
            g_h[gid] = acc;
            g_h16[gid] = __float2half(acc);
        }
    }
}

// e = edge_attr @ We + be -> fp16 in CSR order. Coalesced attr load +
// 16-lane shuffle broadcast (1 gmem load/thread); streaming stores.
__global__ void k_edge_proj(const float* __restrict__ ea,
                            const float* __restrict__ We,
                            const float* __restrict__ be) {
    __shared__ float Ws[EDGE_DIM * HID];
    __shared__ float bs[HID];
    int t = threadIdx.x;
    for (int i = t; i < EDGE_DIM * HID; i += blockDim.x) Ws[i] = We[i];
    if (t < HID) bs[t] = be[t];
    __syncthreads();
    int gid = blockIdx.x * blockDim.x + t;     // exact N_EDGES*16
    int slot = gid >> 4;
    int lane = t & 31;
    int q = lane & 15;
    int half = lane & 16;
    int c = q * 4;
    int edge = g_eorig[slot];
    float a = ea[(size_t)edge * EDGE_DIM + q];
    float a0 = bs[c], a1 = bs[c + 1], a2 = bs[c + 2], a3 = bs[c + 3];
#pragma unroll
    for (int k = 0; k < EDGE_DIM; k++) {
        float ak = __shfl_sync(0xffffffffu, a, half | k);
        const float4 w = *reinterpret_cast<const float4*>(&Ws[k * HID + c]);
        a0 += ak * w.x; a1 += ak * w.y; a2 += ak * w.z; a3 += ak * w.w;
    }
    __half2 p01 = __floats2half2_rn(a0, a1);
    __half2 p23 = __floats2half2_rn(a2, a3);
    uint2 pk;
    pk.x = *reinterpret_cast<unsigned*>(&p01);
    pk.y = *reinterpret_cast<unsigned*>(&p23);
    __stcs(reinterpret_cast<uint2*>(&g_e16[(size_t)slot * HID + c]), pk);
}

// ---------------- CSR build ------------------------------------------------

__global__ void k_hist(const int* __restrict__ ei) {
    int e = blockIdx.x * blockDim.x + threadIdx.x;
    if (e >= N_EDGES) return;
    atomicAdd(&g_deg[ei[N_EDGES + e]], 1);
}

__global__ void k_scan_part() {
    __shared__ int sm[SCAN_CHUNK];
    int t = threadIdx.x;
    int idx = blockIdx.x * SCAN_CHUNK + t;
    int v = (idx < N_NODES) ? g_deg[idx] : 0;
    sm[t] = v;
    __syncthreads();
    for (int off = 128; off > 0; off >>= 1) {
        if (t < off) sm[t] += sm[t + off];
        __syncthreads();
    }
    if (t == 0) g_chunk[blockIdx.x] = sm[0];
}

__global__ void k_scan_top() {
    __shared__ int sm[256];
    int t = threadIdx.x;
    sm[t] = (t < N_CHUNKS) ? g_chunk[t] : 0;
    __syncthreads();
    for (int off = 1; off < 256; off <<= 1) {
        int v = (t >= off) ? sm[t - off] : 0;
        __syncthreads();
        sm[t] += v;
        __syncthreads();
    }
    if (t < N_CHUNKS) g_chunk[t] = (t > 0) ? sm[t - 1] : 0;
    if (t == 0) g_rowptr[N_NODES] = N_EDGES;
}

__global__ void k_scan_final() {
    __shared__ int sm[SCAN_CHUNK];
    int t = threadIdx.x;
    int idx = blockIdx.x * SCAN_CHUNK + t;
    int v = (idx < N_NODES) ? g_deg[idx] : 0;
    sm[t] = v;
    __syncthreads();
    for (int off = 1; off < SCAN_CHUNK; off <<= 1) {
        int u = (t >= off) ? sm[t - off] : 0;
        __syncthreads();
        sm[t] += u;
        __syncthreads();
    }
    if (idx < N_NODES) {
        int r = g_chunk[blockIdx.x] + sm[t] - v;   // exclusive
        g_rowptr[idx] = r;
        g_cursor[idx] = r;
    }
}

__global__ void k_scatter(const int* __restrict__ ei) {
    int e = blockIdx.x * blockDim.x + threadIdx.x;
    if (e >= N_EDGES) return;
    int src = ei[e];
    int dst = ei[N_EDGES + e];
    int pos = atomicAdd(&g_cursor[dst], 1);
    g_src[pos] = src;
    g_eorig[pos] = e;
}

// ---------------- per-layer kernels ----------------------------------------

__device__ __forceinline__ void msg_acc(uint2 ev, uint2 hv, const __half2 zero2,
                                        float& a0, float& a1, float& a2, float& a3) {
    __half2 ma = __hmax2(__hadd2(*reinterpret_cast<__half2*>(&hv.x),
                                 *reinterpret_cast<__half2*>(&ev.x)), zero2);
    __half2 mb = __hmax2(__hadd2(*reinterpret_cast<__half2*>(&hv.y),
                                 *reinterpret_cast<__half2*>(&ev.y)), zero2);
    float2 fa = __half22float2(ma), fb = __half22float2(mb);
    a0 += fa.x; a1 += fa.y; a2 += fb.x; a3 += fb.y;
}

// z[n] = (1+eps)*h[n] + sum_j relu(h16[src_j] + e16_j)
// 16 threads per node, 4 channels each; ldcs on e stream; unroll x4 with
// software-pipelined src prefetch.
__global__ void k_gather(const float* __restrict__ eps, int layer) {
    int t = threadIdx.x;
    int gid = blockIdx.x * blockDim.x + t;
    if (gid >= N_NODES * 16) return;
    int node = gid >> 4;
    int c = (gid & 15) * 4;
    int j = g_rowptr[node];
    int end = g_rowptr[node + 1];
    float a0 = 0.f, a1 = 0.f, a2 = 0.f, a3 = 0.f;
    const __half2 zero2 = __float2half2_rn(0.0f);

    int s0, s1, s2, s3;
    if (j + 4 <= end) {
        s0 = g_src[j]; s1 = g_src[j + 1]; s2 = g_src[j + 2]; s3 = g_src[j + 3];
    }
    for (; j + 4 <= end; ) {
        int c0 = s0, c1 = s1, c2 = s2, c3 = s3;
        int jn = j + 4;
        if (jn + 4 <= end) {
            s0 = g_src[jn]; s1 = g_src[jn + 1]; s2 = g_src[jn + 2]; s3 = g_src[jn + 3];
        }
        uint2 e0 = __ldcs(reinterpret_cast<const uint2*>(&g_e16[(size_t)j * HID + c]));
        uint2 e1 = __ldcs(reinterpret_cast<const uint2*>(&g_e16[(size_t)(j + 1) * HID + c]));
        uint2 e2 = __ldcs(reinterpret_cast<const uint2*>(&g_e16[(size_t)(j + 2) * HID + c]));
        uint2 e3 = __ldcs(reinterpret_cast<const uint2*>(&g_e16[(size_t)(j + 3) * HID + c]));
        uint2 h0 = *reinterpret_cast<const uint2*>(&g_h16[(size_t)c0 * HID + c]);
        uint2 h1 = *reinterpret_cast<const uint2*>(&g_h16[(size_t)c1 * HID + c]);
        uint2 h2 = *reinterpret_cast<const uint2*>(&g_h16[(size_t)c2 * HID + c]);
        uint2 h3 = *reinterpret_cast<const uint2*>(&g_h16[(size_t)c3 * HID + c]);
        msg_acc(e0, h0, zero2, a0, a1, a2, a3);
        msg_acc(e1, h1, zero2, a0, a1, a2, a3);
        msg_acc(e2, h2, zero2, a0, a1, a2, a3);
        msg_acc(e3, h3, zero2, a0, a1, a2, a3);
        j = jn;
    }
    for (; j < end; j++) {
        int sc = g_src[j];
        uint2 e0 = __ldcs(reinterpret_cast<const uint2*>(&g_e16[(size_t)j * HID + c]));
        uint2 h0 = *reinterpret_cast<const uint2*>(&g_h16[(size_t)sc * HID + c]);
        msg_acc(e0, h0, zero2, a0, a1, a2, a3);
    }
    float se = 1.0f + eps[layer];
    float4 hv = *reinterpret_cast<const float4*>(&g_h[(size_t)node * HID + c]);
    float4 z = make_float4(se * hv.x + a0, se * hv.y + a1,
                           se * hv.z + a2, se * hv.w + a3);
    *reinterpret_cast<float4*>(&g_z[(size_t)node * HID + c]) = z;
}

// MLP on tensor cores (tf32, smem pre-converted). 128 nodes/block, 8 warps.
// ONE weight buffer reused W1 -> W2 (smem ~56KB -> 4 blocks/SM).
// zout = relu(z @ W1 + b1) @ W2 + b2 ; accumulates BN sum/sumsq.
__global__ void k_mlp_tc(const float* __restrict__ W1, const float* __restrict__ b1,
                         const float* __restrict__ W2, const float* __restrict__ b2,
                         int layer) {
    extern __shared__ float sm[];
    float* zt   = sm;                      // [128][LDT]
    float* ws   = zt + MLP_TN * LDT;       // [64][LDT] shared W1 then W2
    float* b1s  = ws + HID * LDT;
    float* b2s  = b1s + HID;
    float* ssum = b2s + HID;
    float* ssq  = ssum + HID;

    int t = threadIdx.x;
    for (int i = t; i < HID * HID; i += 256) {
        int r = i >> 6, c = i & 63;
        ws[r * LDT + c] = wmma::__float_to_tf32(W1[i]);
    }
    if (t < HID) { b1s[t] = b1[t]; b2s[t] = b2[t]; ssum[t] = 0.0f; ssq[t] = 0.0f; }
    int node0 = blockIdx.x * MLP_TN;

    for (int i = t; i < MLP_TN * 16; i += 256) {
        int n = i >> 4, kc = (i & 15) * 4;
        int node = node0 + n;
        float4 zv = make_float4(0.f, 0.f, 0.f, 0.f);
        if (node < N_NODES)
            zv = *reinterpret_cast<const float4*>(&g_z[(size_t)node * HID + kc]);
        zt[n * LDT + kc]     = wmma::__float_to_tf32(zv.x);
        zt[n * LDT + kc + 1] = wmma::__float_to_tf32(zv.y);
        zt[n * LDT + kc + 2] = wmma::__float_to_tf32(zv.z);
        zt[n * LDT + kc + 3] = wmma::__float_to_tf32(zv.w);
    }
    __syncthreads();

    int warp = t >> 5, lane = t & 31;
    float* arow = zt + warp * 16 * LDT;

    // ---- GEMM1 (W1 in ws) ----
    wmma::fragment<wmma::accumulator, 16, 16, 8, float> cf[4];
#pragma unroll
    for (int nt = 0; nt < 4; nt++) wmma::fill_fragment(cf[nt], 0.0f);
#pragma unroll
    for (int k = 0; k < HID; k += 8) {
        wmma::fragment<wmma::matrix_a, 16, 16, 8, wmma::precision::tf32, wmma::row_major> af;
        wmma::load_matrix_sync(af, arow + k, LDT);
#pragma unroll
        for (int nt = 0; nt < 4; nt++) {
            wmma::fragment<wmma::matrix_b, 16, 16, 8, wmma::precision::tf32, wmma::row_major> bf;
            wmma::load_matrix_sync(bf, ws + k * LDT + nt * 16, LDT);
            wmma::mma_sync(cf[nt], af, bf, cf[nt]);
        }
    }
#pragma unroll
    for (int nt = 0; nt < 4; nt++)
        wmma::store_matrix_sync(arow + nt * 16, cf[nt], LDT, wmma::mem_row_major);
    // all warps done reading W1 from ws before overwrite
    __syncthreads();
    // overwrite ws with W2
    for (int i = t; i < HID * HID; i += 256) {
        int r = i >> 6, c = i & 63;
        ws[r * LDT + c] = wmma::__float_to_tf32(W2[i]);
    }
    // bias + relu + tf32-round on own strip (no cross-warp deps on zt)
    for (int i = lane; i < 16 * HID; i += 32) {
        int r = i >> 6, c = i & 63;
        arow[r * LDT + c] = wmma::__float_to_tf32(fmaxf(arow[r * LDT + c] + b1s[c], 0.0f));
    }
    __syncthreads();

    // ---- GEMM2 (W2 in ws) ----
#pragma unroll
    for (int nt = 0; nt < 4; nt++) wmma::fill_fragment(cf[nt], 0.0f);
#pragma unroll
    for (int k = 0; k < HID; k += 8) {
        wmma::fragment<wmma::matrix_a, 16, 16, 8, wmma::precision::tf32, wmma::row_major> af;
        wmma::load_matrix_sync(af, arow + k, LDT);
#pragma unroll
        for (int nt = 0; nt < 4; nt++) {
            wmma::fragment<wmma::matrix_b, 16, 16, 8, wmma::precision::tf32, wmma::row_major> bf;
            wmma::load_matrix_sync(bf, ws + k * LDT + nt * 16, LDT);
            wmma::mma_sync(cf[nt], af, bf, cf[nt]);
        }
    }
#pragma unroll
    for (int nt = 0; nt < 4; nt++)
        wmma::store_matrix_sync(arow + nt * 16, cf[nt], LDT, wmma::mem_row_major);
    __syncwarp();

#pragma unroll
    for (int half = 0; half < 2; half++) {
        int c = lane + half * 32;
        float s = 0.f, q = 0.f;
#pragma unroll
        for (int r = 0; r < 16; r++) {
            int node = node0 + warp * 16 + r;
            if (node < N_NODES) {
                float v = arow[r * LDT + c] + b2s[c];
                g_zout[(size_t)node * HID + c] = v;
                s += v; q += v * v;
            }
        }
        atomicAdd(&ssum[c], s);
        atomicAdd(&ssq[c], q);
    }
    __syncthreads();
    if (t < HID) {
        atomicAdd(&g_stats[2 * HID * layer + t], ssum[t]);
        atomicAdd(&g_stats[2 * HID * layer + HID + t], ssq[t]);
    }
}

// h = relu(gamma*(zout - mu)*inv_std + beta) + h ; writes fp32 (+ fp16 unless last).
// If last layer, fuse pooling instead.
__global__ void k_bnapply(const float* __restrict__ gamma,
                          const float* __restrict__ beta,
                          const int* __restrict__ batch, int layer, int do_pool) {
    int gid = blockIdx.x * blockDim.x + threadIdx.x;
    if (gid >= N_NODES * 16) return;
    int c = (gid & 15) * 4;
    const float* st = g_stats + 2 * HID * layer;
    const float invN = 1.0f / (float)N_NODES;
    float4 v = *reinterpret_cast<const float4*>(&g_zout[(size_t)gid * 4]);
    float4 h = *reinterpret_cast<const float4*>(&g_h[(size_t)gid * 4]);
    float r[4] = {v.x, v.y, v.z, v.w};
    float hh[4] = {h.x, h.y, h.z, h.w};
#pragma unroll
    for (int j = 0; j < 4; j++) {
        float mu = st[c + j] * invN;
        float var = st[HID + c + j] * invN - mu * mu;
        float inv = rsqrtf(var + BN_EPS);
        float tt = gamma[c + j] * (r[j] - mu) * inv + beta[c + j];
        r[j] = fmaxf(tt, 0.0f) + hh[j];
    }
    *reinterpret_cast<float4*>(&g_h[(size_t)gid * 4]) = make_float4(r[0], r[1], r[2], r[3]);
    if (!do_pool) {
        __half2 p01 = __floats2half2_rn(r[0], r[1]);
        __half2 p23 = __floats2half2_rn(r[2], r[3]);
        uint2 pk;
        pk.x = *reinterpret_cast<unsigned*>(&p01);
        pk.y = *reinterpret_cast<unsigned*>(&p23);
        *reinterpret_cast<uint2*>(&g_h16[(size_t)gid * 4]) = pk;
    } else {
        int n = gid >> 4;
        int b = batch[n];
        float* p = &g_pool[b * HID + c];
        asm volatile("red.global.add.v4.f32 [%0], {%1, %2, %3, %4};"
                     :: "l"(p), "f"(r[0]), "f"(r[1]), "f"(r[2]), "f"(r[3]) : "memory");
        if ((gid & 15) == 0)
            asm volatile("red.global.add.f32 [%0], %1;" :: "l"(&g_cnt[b]), "f"(1.0f) : "memory");
    }
}

// classifier: one block (64 threads) per graph
__global__ void k_cls(const float* __restrict__ W1, const float* __restrict__ b1,
                      const float* __restrict__ W2, const float* __restrict__ b2,
                      float* __restrict__ out) {
    __shared__ float pr[HID];
    __shared__ float aw[HID];
    int g = blockIdx.x;
    int t = threadIdx.x;
    float cnt = fmaxf(g_cnt[g], 1.0f);
    pr[t] = g_pool[g * HID + t] / cnt;
    __syncthreads();
    float acc = b1[t];
#pragma unroll 8
    for (int k = 0; k < HID; k++) acc += pr[k] * W1[k * HID + t];
    aw[t] = fmaxf(acc, 0.0f);
    __syncthreads();
    if (t < N_CLASSES) {
        float o = b2[t];
#pragma unroll 8
        for (int k = 0; k < HID; k++) o += aw[k] * W2[k * N_CLASSES + t];
        float prob = 1.0f / (1.0f + expf(-o));
        float pred = (prob > 0.5f) ? 1.0f : 0.0f;
        int idx = g * N_CLASSES + t;
        out[idx] = o;
        out[N_GRAPHS * N_CLASSES + idx] = prob;
        out[2 * N_GRAPHS * N_CLASSES + idx] = pred;
        out[3 * N_GRAPHS * N_CLASSES + idx] = pred;
    }
}

// ---------------- launch --------------------------------------------------
extern "C" void kernel_launch(void* const* d_in, const int* in_sizes, int n_in,
                              void* d_out, int out_size) {
    const float* x      = (const float*)d_in[0];
    const int*   ei     = (const int*)  d_in[1];
    const int*   batch  = (const int*)  d_in[2];
    const float* ea     = (const float*)d_in[3];
    const float* Wn     = (const float*)d_in[4];
    const float* bn     = (const float*)d_in[5];
    const float* We     = (const float*)d_in[6];
    const float* be     = (const float*)d_in[7];
    const float* eps    = (const float*)d_in[8];
    const float* mlp_W1 = (const float*)d_in[9];
    const float* mlp_b1 = (const float*)d_in[10];
    const float* mlp_W2 = (const float*)d_in[11];
    const float* mlp_b2 = (const float*)d_in[12];
    const float* bn_g   = (const float*)d_in[13];
    const float* bn_b   = (const float*)d_in[14];
    const float* cls_W1 = (const float*)d_in[15];
    const float* cls_b1 = (const float*)d_in[16];
    const float* cls_W2 = (const float*)d_in[17];
    const float* cls_b2 = (const float*)d_in[18];
    float* out = (float*)d_out;

    const int TPB = 256;
    const int np_blocks     = (N_NODES + NP_NODES - 1) / NP_NODES;  // 3125
    const int node4_blocks  = (N_NODES * 16 + TPB - 1) / TPB;    // 3125
    const int edge16_blocks = (N_EDGES * 16) / TPB;              // 100000
    const int edge_blocks   = (N_EDGES + TPB - 1) / TPB;         // 6250
    const int mlp_blocks    = (N_NODES + MLP_TN - 1) / MLP_TN;   // 391
    const int mlp_smem      = (MLP_TN * LDT + HID * LDT + 4 * HID) * sizeof(float);
    const int init_blocks   = (N_NODES + TPB - 1) / TPB;         // 196 (covers all)

    static bool attr_set = false;
    if (!attr_set) {
        cudaFuncSetAttribute(k_mlp_tc, cudaFuncAttributeMaxDynamicSharedMemorySize, mlp_smem);
        attr_set = true;
    }

    k_init<<<init_blocks, TPB>>>();
    k_node_proj<<<np_blocks, TPB>>>(x, Wn, bn);
    k_hist<<<edge_blocks, TPB>>>(ei);
    k_scan_part<<<N_CHUNKS, SCAN_CHUNK>>>();
    k_scan_top<<<1, 256>>>();
    k_scan_final<<<N_CHUNKS, SCAN_CHUNK>>>();
    k_scatter<<<edge_blocks, TPB>>>(ei);
    k_edge_proj<<<edge16_blocks, TPB>>>(ea, We, be);

    for (int l = 0; l < N_LAYERS; l++) {
        k_gather<<<node4_blocks, TPB>>>(eps, l);
        k_mlp_tc<<<mlp_blocks, TPB, mlp_smem>>>(mlp_W1 + l * HID * HID, mlp_b1 + l * HID,
                                                mlp_W2 + l * HID * HID, mlp_b2 + l * HID, l);
        k_bnapply<<<node4_blocks, TPB>>>(bn_g + l * HID, bn_b + l * HID,
                                         batch, l, (l == N_LAYERS - 1) ? 1 : 0);
    }

    k_cls<<<N_GRAPHS, HID>>>(cls_W1, cls_b1, cls_W2, cls_b2, out);
}